// round 1
// baseline (speedup 1.0000x reference)
#include <cuda_runtime.h>
#include <cuda_bf16.h>
#include <math.h>

// Problem constants (fixed by setup_inputs)
#define BB 4
#define SS 2048
#define HH 1024
#define NH 16
#define HD 64
#define MROWS (BB * SS)          // 8192
#define LN_EPS 1e-5f

// ---------------------------------------------------------------------------
// Scratch (device globals: no allocation allowed in kernel_launch)
// ---------------------------------------------------------------------------
__device__ float g_y[MROWS * HH];        // LayerNorm output         (32 MB)
__device__ float g_qkv[MROWS * 3 * HH];  // fused QKV projection     (96 MB)
__device__ float g_ctx[MROWS * HH];      // attention context        (32 MB)

// ---------------------------------------------------------------------------
// LayerNorm: one block per row (H=1024), 256 threads, float4 per thread
// ---------------------------------------------------------------------------
__device__ __forceinline__ float block_reduce_sum_256(float v, float* sbuf) {
    #pragma unroll
    for (int off = 16; off > 0; off >>= 1)
        v += __shfl_xor_sync(0xffffffffu, v, off);
    int wid = threadIdx.x >> 5;
    if ((threadIdx.x & 31) == 0) sbuf[wid] = v;
    __syncthreads();
    if (threadIdx.x < 32) {
        float t = (threadIdx.x < 8) ? sbuf[threadIdx.x] : 0.0f;
        #pragma unroll
        for (int off = 4; off > 0; off >>= 1)
            t += __shfl_xor_sync(0xffffffffu, t, off);
        if (threadIdx.x == 0) sbuf[0] = t;
    }
    __syncthreads();
    float r = sbuf[0];
    __syncthreads();  // allow sbuf reuse
    return r;
}

__global__ __launch_bounds__(256) void ln_kernel(const float* __restrict__ x,
                                                 const float* __restrict__ gamma,
                                                 const float* __restrict__ beta) {
    __shared__ float sbuf[8];
    int row = blockIdx.x;
    int t = threadIdx.x;
    const float4* xr = (const float4*)(x + (size_t)row * HH);
    float4 v = xr[t];                       // 256 threads * 4 = 1024
    float s = v.x + v.y + v.z + v.w;
    s = block_reduce_sum_256(s, sbuf);
    float mu = s * (1.0f / HH);
    float dx0 = v.x - mu, dx1 = v.y - mu, dx2 = v.z - mu, dx3 = v.w - mu;
    float sq = dx0 * dx0 + dx1 * dx1 + dx2 * dx2 + dx3 * dx3;
    sq = block_reduce_sum_256(sq, sbuf);
    float rstd = rsqrtf(sq * (1.0f / HH) + LN_EPS);
    float4 gg = ((const float4*)gamma)[t];
    float4 bb = ((const float4*)beta)[t];
    float4 o;
    o.x = dx0 * rstd * gg.x + bb.x;
    o.y = dx1 * rstd * gg.y + bb.y;
    o.z = dx2 * rstd * gg.z + bb.z;
    o.w = dx3 * rstd * gg.w + bb.w;
    ((float4*)(g_y + (size_t)row * HH))[t] = o;
}

// ---------------------------------------------------------------------------
// SGEMM: C[m][n] = (RESID? X[m][n]:0) + bias[n] + sum_k A[m][k]*W[n][k]
// Tiles 128x128x32, 256 threads, 8x8 per thread, cyclic stride-16 mapping.
// smem pad 33 (= 1 mod 32 banks) -> conflict-free fragment loads.
// ---------------------------------------------------------------------------
template <int M, int N, int K, bool RESID>
__global__ __launch_bounds__(256) void gemm_kernel(const float* __restrict__ A,
                                                   const float* __restrict__ W,
                                                   const float* __restrict__ bias,
                                                   const float* __restrict__ resid,
                                                   float* __restrict__ C) {
    const int BM = 128, BN = 128, BK = 32, PAD = 33;
    __shared__ float As[BM * PAD];
    __shared__ float Bs[BN * PAD];
    int m0 = blockIdx.y * BM;
    int n0 = blockIdx.x * BN;
    int tid = threadIdx.x;
    int tx = tid & 15, ty = tid >> 4;

    float acc[8][8];
    #pragma unroll
    for (int i = 0; i < 8; i++)
        #pragma unroll
        for (int j = 0; j < 8; j++) acc[i][j] = 0.0f;

    for (int k0 = 0; k0 < K; k0 += BK) {
        // Load tiles: 128x32 floats each = 1024 float4, 4 per thread per matrix
        #pragma unroll
        for (int i = 0; i < 4; i++) {
            int lin4 = tid + i * 256;        // float4 index
            int r = lin4 >> 3;               // 8 float4 per row
            int c = (lin4 & 7) << 2;
            float4 a = *(const float4*)&A[(size_t)(m0 + r) * K + k0 + c];
            float4 b = *(const float4*)&W[(size_t)(n0 + r) * K + k0 + c];
            float* ad = &As[r * PAD + c];
            ad[0] = a.x; ad[1] = a.y; ad[2] = a.z; ad[3] = a.w;
            float* bd = &Bs[r * PAD + c];
            bd[0] = b.x; bd[1] = b.y; bd[2] = b.z; bd[3] = b.w;
        }
        __syncthreads();
        #pragma unroll
        for (int kk = 0; kk < BK; kk++) {
            float ra[8], rb[8];
            #pragma unroll
            for (int i = 0; i < 8; i++) ra[i] = As[(ty + i * 16) * PAD + kk];
            #pragma unroll
            for (int j = 0; j < 8; j++) rb[j] = Bs[(tx + j * 16) * PAD + kk];
            #pragma unroll
            for (int i = 0; i < 8; i++)
                #pragma unroll
                for (int j = 0; j < 8; j++) acc[i][j] += ra[i] * rb[j];
        }
        __syncthreads();
    }

    #pragma unroll
    for (int i = 0; i < 8; i++) {
        int m = m0 + ty + i * 16;
        #pragma unroll
        for (int j = 0; j < 8; j++) {
            int n = n0 + tx + j * 16;
            float v = acc[i][j] + bias[n];
            if (RESID) v += resid[(size_t)m * N + n];
            C[(size_t)m * N + n] = v;
        }
    }
}

// ---------------------------------------------------------------------------
// Flash attention: grid (S/64, NH, B), 256 threads.
// Q tile 64x64 in smem; stream K/V tiles of 32 rows; online softmax.
// Score phase: thread (tx,ty) owns rows ty*4+i (i<4), cols tx*2+j (j<2).
// PV phase  : thread owns rows ty*4+i, dims tx*4+j (j<4).
// sKP is a union: K tile [32][65] (scores) then P tile [64][33] (PV).
// ---------------------------------------------------------------------------
#define TQ 64
#define TK 32

__global__ __launch_bounds__(256) void attn_kernel(const int* __restrict__ mask) {
    __shared__ float Qs[TQ * HD];     // [64][64]
    __shared__ float sKP[TQ * 33];    // union: K [32][65]=2080 / P [64][33]=2112
    __shared__ float Vs[TK * HD];     // [32][64]

    int tid = threadIdx.x;
    int tx = tid & 15, ty = tid >> 4;
    int qt = blockIdx.x, h = blockIdx.y, b = blockIdx.z;
    int q0 = qt * TQ;
    int rowbase = b * SS;
    const int LD = 3 * HH;
    const float* qkv = g_qkv;

    // Load Q tile
    #pragma unroll
    for (int i = 0; i < 4; i++) {
        int lin = tid + i * 256;
        int r = lin >> 4;
        int c = (lin & 15) << 2;
        *(float4*)&Qs[r * HD + c] =
            *(const float4*)&qkv[(size_t)(rowbase + q0 + r) * LD + h * HD + c];
    }

    float m_i[4], l_i[4], O[4][4];
    #pragma unroll
    for (int i = 0; i < 4; i++) {
        m_i[i] = -1e30f; l_i[i] = 0.0f;
        #pragma unroll
        for (int j = 0; j < 4; j++) O[i][j] = 0.0f;
    }

    for (int kt = 0; kt < SS / TK; kt++) {
        int k0 = kt * TK;
        __syncthreads();  // prev PV readers done (also orders first Q use)
        // Load K tile into sKP ([32][65]) and V tile into Vs ([32][64])
        #pragma unroll
        for (int i = 0; i < 2; i++) {
            int lin = tid + i * 256;
            int r = lin >> 4;
            int c = (lin & 15) << 2;
            const float* base = &qkv[(size_t)(rowbase + k0 + r) * LD + h * HD + c];
            float4 kv = *(const float4*)(base + HH);
            float4 vv = *(const float4*)(base + 2 * HH);
            float* kd = &sKP[r * 65 + c];
            kd[0] = kv.x; kd[1] = kv.y; kd[2] = kv.z; kd[3] = kv.w;
            *(float4*)&Vs[r * HD + c] = vv;
        }
        __syncthreads();

        // Scores: 4 rows x 2 cols per thread
        float sc[4][2];
        #pragma unroll
        for (int i = 0; i < 4; i++) { sc[i][0] = 0.0f; sc[i][1] = 0.0f; }
        #pragma unroll 8
        for (int kk = 0; kk < HD; kk++) {
            float qa[4];
            #pragma unroll
            for (int i = 0; i < 4; i++) qa[i] = Qs[(ty * 4 + i) * HD + kk];
            float kb0 = sKP[(tx * 2) * 65 + kk];
            float kb1 = sKP[(tx * 2 + 1) * 65 + kk];
            #pragma unroll
            for (int i = 0; i < 4; i++) {
                sc[i][0] += qa[i] * kb0;
                sc[i][1] += qa[i] * kb1;
            }
        }
        float bj0 = (float)mask[b * SS + k0 + tx * 2]     * -1e8f;
        float bj1 = (float)mask[b * SS + k0 + tx * 2 + 1] * -1e8f;

        __syncthreads();  // all K reads done before P overwrites sKP

        float pr[4][2];
        #pragma unroll
        for (int i = 0; i < 4; i++) {
            float s0 = sc[i][0] * 0.125f + bj0;
            float s1 = sc[i][1] * 0.125f + bj1;
            float rm = fmaxf(s0, s1);
            #pragma unroll
            for (int off = 8; off > 0; off >>= 1)
                rm = fmaxf(rm, __shfl_xor_sync(0xffffffffu, rm, off));
            float mnew = fmaxf(m_i[i], rm);
            float p0 = __expf(s0 - mnew);
            float p1 = __expf(s1 - mnew);
            float rs = p0 + p1;
            #pragma unroll
            for (int off = 8; off > 0; off >>= 1)
                rs += __shfl_xor_sync(0xffffffffu, rs, off);
            float corr = __expf(m_i[i] - mnew);
            l_i[i] = l_i[i] * corr + rs;
            m_i[i] = mnew;
            #pragma unroll
            for (int j = 0; j < 4; j++) O[i][j] *= corr;
            pr[i][0] = p0; pr[i][1] = p1;
        }
        #pragma unroll
        for (int i = 0; i < 4; i++) {
            sKP[(ty * 4 + i) * 33 + tx * 2]     = pr[i][0];
            sKP[(ty * 4 + i) * 33 + tx * 2 + 1] = pr[i][1];
        }
        __syncthreads();

        // PV: O[r][d] += sum_c P[r][c] * V[c][d]
        #pragma unroll 4
        for (int c = 0; c < TK; c++) {
            float vv[4];
            #pragma unroll
            for (int j = 0; j < 4; j++) vv[j] = Vs[c * HD + tx * 4 + j];
            #pragma unroll
            for (int i = 0; i < 4; i++) {
                float p = sKP[(ty * 4 + i) * 33 + c];
                #pragma unroll
                for (int j = 0; j < 4; j++) O[i][j] += p * vv[j];
            }
        }
    }

    // Epilogue: normalize and write ctx[b, s, h*64 + d]
    #pragma unroll
    for (int i = 0; i < 4; i++) {
        float inv = 1.0f / l_i[i];
        int row = rowbase + q0 + ty * 4 + i;
        float* op = &g_ctx[(size_t)row * HH + h * HD + tx * 4];
        op[0] = O[i][0] * inv;
        op[1] = O[i][1] * inv;
        op[2] = O[i][2] * inv;
        op[3] = O[i][3] * inv;
    }
}

// ---------------------------------------------------------------------------
// Launch
// ---------------------------------------------------------------------------
extern "C" void kernel_launch(void* const* d_in, const int* in_sizes, int n_in,
                              void* d_out, int out_size) {
    (void)in_sizes; (void)n_in; (void)out_size;
    const float* x      = (const float*)d_in[0];
    const int*   mask   = (const int*)d_in[1];
    const float* qkv_w  = (const float*)d_in[2];
    const float* qkv_b  = (const float*)d_in[3];
    const float* out_w  = (const float*)d_in[4];
    const float* out_b  = (const float*)d_in[5];
    const float* gamma  = (const float*)d_in[6];
    const float* beta   = (const float*)d_in[7];
    float* out = (float*)d_out;

    // Resolve scratch addresses (pure queries; capture-safe, no allocation)
    float *py = nullptr, *pqkv = nullptr, *pctx = nullptr;
    cudaGetSymbolAddress((void**)&py,   g_y);
    cudaGetSymbolAddress((void**)&pqkv, g_qkv);
    cudaGetSymbolAddress((void**)&pctx, g_ctx);

    // 1) pre-LayerNorm
    ln_kernel<<<MROWS, 256>>>(x, gamma, beta);

    // 2) QKV projection: [8192,1024] @ [3072,1024]^T + b -> [8192,3072]
    gemm_kernel<MROWS, 3 * HH, HH, false>
        <<<dim3(3 * HH / 128, MROWS / 128), 256>>>(py, qkv_w, qkv_b, nullptr, pqkv);

    // 3) Flash attention -> g_ctx
    attn_kernel<<<dim3(SS / TQ, NH, BB), 256>>>(mask);

    // 4) Output projection + bias + residual
    gemm_kernel<MROWS, HH, HH, true>
        <<<dim3(HH / 128, MROWS / 128), 256>>>(pctx, out_w, out_b, x, out);
}

// round 2
// speedup vs baseline: 3.1587x; 3.1587x over previous
#include <cuda_runtime.h>
#include <cuda_bf16.h>
#include <math.h>
#include <stdint.h>

// Problem constants (fixed by setup_inputs)
#define BB 4
#define SS 2048
#define HH 1024
#define NH 16
#define HD 64
#define MROWS (BB * SS)          // 8192
#define LN_EPS 1e-5f

// ---------------------------------------------------------------------------
// Scratch (device globals: no allocation allowed in kernel_launch)
// ---------------------------------------------------------------------------
__device__ float g_y[MROWS * HH];        // LayerNorm output
__device__ float g_qkv[MROWS * 3 * HH];  // fused QKV projection
__device__ float g_ctx[MROWS * HH];      // attention context

// ---------------------------------------------------------------------------
// TF32 helpers
// ---------------------------------------------------------------------------
__device__ __forceinline__ uint32_t f2tf32(float x) {
    uint32_t o;
    asm("cvt.rna.tf32.f32 %0, %1;" : "=r"(o) : "f"(x));
    return o;
}

// D += A*B, m16n8k8, tf32 inputs, fp32 accumulate
__device__ __forceinline__ void mma_tf32(float* c, const uint32_t* a, const uint32_t* b) {
    asm volatile(
        "mma.sync.aligned.m16n8k8.row.col.f32.tf32.tf32.f32 "
        "{%0,%1,%2,%3}, {%4,%5,%6,%7}, {%8,%9}, {%0,%1,%2,%3};"
        : "+f"(c[0]), "+f"(c[1]), "+f"(c[2]), "+f"(c[3])
        : "r"(a[0]), "r"(a[1]), "r"(a[2]), "r"(a[3]), "r"(b[0]), "r"(b[1]));
}

// ---------------------------------------------------------------------------
// LayerNorm: one block per row (H=1024), 256 threads, float4 per thread
// ---------------------------------------------------------------------------
__device__ __forceinline__ float block_reduce_sum_256(float v, float* sbuf) {
    #pragma unroll
    for (int off = 16; off > 0; off >>= 1)
        v += __shfl_xor_sync(0xffffffffu, v, off);
    int wid = threadIdx.x >> 5;
    if ((threadIdx.x & 31) == 0) sbuf[wid] = v;
    __syncthreads();
    if (threadIdx.x < 32) {
        float t = (threadIdx.x < 8) ? sbuf[threadIdx.x] : 0.0f;
        #pragma unroll
        for (int off = 4; off > 0; off >>= 1)
            t += __shfl_xor_sync(0xffffffffu, t, off);
        if (threadIdx.x == 0) sbuf[0] = t;
    }
    __syncthreads();
    float r = sbuf[0];
    __syncthreads();
    return r;
}

__global__ __launch_bounds__(256) void ln_kernel(const float* __restrict__ x,
                                                 const float* __restrict__ gamma,
                                                 const float* __restrict__ beta) {
    __shared__ float sbuf[8];
    int row = blockIdx.x;
    int t = threadIdx.x;
    const float4* xr = (const float4*)(x + (size_t)row * HH);
    float4 v = xr[t];
    float s = v.x + v.y + v.z + v.w;
    s = block_reduce_sum_256(s, sbuf);
    float mu = s * (1.0f / HH);
    float dx0 = v.x - mu, dx1 = v.y - mu, dx2 = v.z - mu, dx3 = v.w - mu;
    float sq = dx0 * dx0 + dx1 * dx1 + dx2 * dx2 + dx3 * dx3;
    sq = block_reduce_sum_256(sq, sbuf);
    float rstd = rsqrtf(sq * (1.0f / HH) + LN_EPS);
    float4 gg = ((const float4*)gamma)[t];
    float4 bb = ((const float4*)beta)[t];
    float4 o;
    o.x = dx0 * rstd * gg.x + bb.x;
    o.y = dx1 * rstd * gg.y + bb.y;
    o.z = dx2 * rstd * gg.z + bb.z;
    o.w = dx3 * rstd * gg.w + bb.w;
    ((float4*)(g_y + (size_t)row * HH))[t] = o;
}

// ---------------------------------------------------------------------------
// TF32 tensor-core GEMM: C[m][n] = (RESID? X:0) + bias[n] + sum_k A[m][k]*W[n][k]
// Block tile 128x128, BK=32, 256 threads = 8 warps, warp tile 64x32.
// smem [row][k] layout with stride 36 (== 4 mod 32) -> conflict-free frag LDS.
// ---------------------------------------------------------------------------
template <int N, int K, bool RESID>
__global__ __launch_bounds__(256) void gemm_tc_kernel(const float* __restrict__ A,
                                                      const float* __restrict__ W,
                                                      const float* __restrict__ bias,
                                                      const float* __restrict__ resid,
                                                      float* __restrict__ C) {
    const int PAD = 36;
    __shared__ uint32_t As[128 * PAD];
    __shared__ uint32_t Bs[128 * PAD];

    int m0 = blockIdx.y * 128;
    int n0 = blockIdx.x * 128;
    int tid = threadIdx.x;
    int warp = tid >> 5;
    int lane = tid & 31;
    int gid = lane >> 2;   // group id (0..7)
    int tig = lane & 3;    // thread in group
    int wm = warp >> 2;    // 0..1 -> 64 rows
    int wn = warp & 3;     // 0..3 -> 32 cols

    float acc[4][4][4];
    #pragma unroll
    for (int i = 0; i < 4; i++)
        #pragma unroll
        for (int j = 0; j < 4; j++)
            #pragma unroll
            for (int r = 0; r < 4; r++) acc[i][j][r] = 0.0f;

    for (int k0 = 0; k0 < K; k0 += 32) {
        __syncthreads();
        // Fill As/Bs: 128 rows x 32 k each, tf32-rounded, uint4 stores
        #pragma unroll
        for (int i = 0; i < 4; i++) {
            int lin4 = tid + i * 256;
            int r = lin4 >> 3;
            int c = (lin4 & 7) << 2;
            float4 a = *(const float4*)&A[(size_t)(m0 + r) * K + k0 + c];
            float4 b = *(const float4*)&W[(size_t)(n0 + r) * K + k0 + c];
            uint4 at = make_uint4(f2tf32(a.x), f2tf32(a.y), f2tf32(a.z), f2tf32(a.w));
            uint4 bt = make_uint4(f2tf32(b.x), f2tf32(b.y), f2tf32(b.z), f2tf32(b.w));
            *(uint4*)&As[r * PAD + c] = at;
            *(uint4*)&Bs[r * PAD + c] = bt;
        }
        __syncthreads();

        #pragma unroll
        for (int ks = 0; ks < 4; ks++) {
            int kb = ks * 8;
            uint32_t af[4][4];
            #pragma unroll
            for (int tm = 0; tm < 4; tm++) {
                int m = wm * 64 + tm * 16 + gid;
                af[tm][0] = As[m * PAD + kb + tig];
                af[tm][1] = As[(m + 8) * PAD + kb + tig];
                af[tm][2] = As[m * PAD + kb + tig + 4];
                af[tm][3] = As[(m + 8) * PAD + kb + tig + 4];
            }
            #pragma unroll
            for (int tn = 0; tn < 4; tn++) {
                int n = wn * 32 + tn * 8 + gid;
                uint32_t bf[2];
                bf[0] = Bs[n * PAD + kb + tig];
                bf[1] = Bs[n * PAD + kb + tig + 4];
                #pragma unroll
                for (int tm = 0; tm < 4; tm++) mma_tf32(acc[tm][tn], af[tm], bf);
            }
        }
    }

    // Epilogue: c-frag rows gid/gid+8, cols 2*tig/2*tig+1
    #pragma unroll
    for (int tm = 0; tm < 4; tm++) {
        int m = m0 + wm * 64 + tm * 16 + gid;
        #pragma unroll
        for (int tn = 0; tn < 4; tn++) {
            int n = n0 + wn * 32 + tn * 8 + 2 * tig;
            float b0 = bias[n], b1 = bias[n + 1];
            float v0 = acc[tm][tn][0] + b0;
            float v1 = acc[tm][tn][1] + b1;
            float v2 = acc[tm][tn][2] + b0;
            float v3 = acc[tm][tn][3] + b1;
            if (RESID) {
                v0 += resid[(size_t)m * N + n];
                v1 += resid[(size_t)m * N + n + 1];
                v2 += resid[(size_t)(m + 8) * N + n];
                v3 += resid[(size_t)(m + 8) * N + n + 1];
            }
            *(float2*)&C[(size_t)m * N + n] = make_float2(v0, v1);
            *(float2*)&C[(size_t)(m + 8) * N + n] = make_float2(v2, v3);
        }
    }
}

// ---------------------------------------------------------------------------
// Flash attention with tf32 mma. Grid (S/64, NH, B), 128 threads = 4 warps.
// Each warp owns 16 q-rows. K-tiles of 32 rows, online softmax.
// Qs: [64][68] (stride 68 == 4 mod 32, conflict-free A frags)
// KPs union: K [32][68] during scores / P [64][36] during PV
// Vs: [32][72] (stride 72 == 8 mod 32, conflict-free B frags)
// ---------------------------------------------------------------------------
#define TQ 64
#define TK 32
#define QSTR 68
#define PSTR 36
#define VSTR 72

__global__ __launch_bounds__(128) void attn_kernel(const int* __restrict__ mask) {
    __shared__ uint32_t Qs[TQ * QSTR];                 // 17.4 KB
    __shared__ uint32_t KPs[TQ * PSTR];                // union: 2304 words >= 32*68
    __shared__ uint32_t Vs[TK * VSTR];                 // 9.2 KB

    int tid = threadIdx.x;
    int warp = tid >> 5;
    int lane = tid & 31;
    int gid = lane >> 2;
    int tig = lane & 3;
    int qt = blockIdx.x, h = blockIdx.y, b = blockIdx.z;
    int q0 = qt * TQ;
    int rowbase = b * SS;
    const int LD = 3 * HH;
    const float* qkv = g_qkv;
    int wrow = warp * 16;   // this warp's q-row base within tile

    // Load Q tile (tf32-rounded)
    #pragma unroll
    for (int i = 0; i < 8; i++) {
        int lin = tid + i * 128;
        int r = lin >> 4;
        int c = (lin & 15) << 2;
        float4 q = *(const float4*)&qkv[(size_t)(rowbase + q0 + r) * LD + h * HD + c];
        uint4 qb = make_uint4(f2tf32(q.x), f2tf32(q.y), f2tf32(q.z), f2tf32(q.w));
        *(uint4*)&Qs[r * QSTR + c] = qb;
    }

    float m_i[2], l_i[2];
    float of[8][4];
    m_i[0] = -1e30f; m_i[1] = -1e30f;
    l_i[0] = 0.0f;   l_i[1] = 0.0f;
    #pragma unroll
    for (int t = 0; t < 8; t++)
        #pragma unroll
        for (int r = 0; r < 4; r++) of[t][r] = 0.0f;

    for (int kt = 0; kt < SS / TK; kt++) {
        int k0 = kt * TK;
        __syncthreads();   // prior iter readers done (also first-iter Q fill)
        // Fill K tile -> KPs (stride QSTR) and V tile -> Vs (stride VSTR)
        #pragma unroll
        for (int i = 0; i < 4; i++) {
            int lin = tid + i * 128;
            int r = lin >> 4;
            int c = (lin & 15) << 2;
            const float* base = &qkv[(size_t)(rowbase + k0 + r) * LD + h * HD + c];
            float4 kv = *(const float4*)(base + HH);
            float4 vv = *(const float4*)(base + 2 * HH);
            uint4 kb = make_uint4(f2tf32(kv.x), f2tf32(kv.y), f2tf32(kv.z), f2tf32(kv.w));
            uint4 vb = make_uint4(f2tf32(vv.x), f2tf32(vv.y), f2tf32(vv.z), f2tf32(vv.w));
            *(uint4*)&KPs[r * QSTR + c] = kb;
            *(uint4*)&Vs[r * VSTR + c] = vb;
        }
        __syncthreads();

        // Scores: m16 x n32, k=64 -> 8 ksteps x 4 ntiles
        float sf[4][4];
        #pragma unroll
        for (int t = 0; t < 4; t++)
            #pragma unroll
            for (int r = 0; r < 4; r++) sf[t][r] = 0.0f;

        #pragma unroll
        for (int ks = 0; ks < 8; ks++) {
            int kb = ks * 8;
            uint32_t af[4];
            af[0] = Qs[(wrow + gid) * QSTR + kb + tig];
            af[1] = Qs[(wrow + gid + 8) * QSTR + kb + tig];
            af[2] = Qs[(wrow + gid) * QSTR + kb + tig + 4];
            af[3] = Qs[(wrow + gid + 8) * QSTR + kb + tig + 4];
            #pragma unroll
            for (int t = 0; t < 4; t++) {
                uint32_t bf[2];
                bf[0] = KPs[(t * 8 + gid) * QSTR + kb + tig];
                bf[1] = KPs[(t * 8 + gid) * QSTR + kb + tig + 4];
                mma_tf32(sf[t], af, bf);
            }
        }

        __syncthreads();   // all warps done reading K before P overwrites union

        // Mask bias for this thread's columns
        float mb[4][2];
        #pragma unroll
        for (int t = 0; t < 4; t++) {
            int col = k0 + t * 8 + 2 * tig;
            mb[t][0] = (float)mask[b * SS + col] * -1e8f;
            mb[t][1] = (float)mask[b * SS + col + 1] * -1e8f;
        }

        // scale + bias
        float sv[4][4];
        #pragma unroll
        for (int t = 0; t < 4; t++) {
            sv[t][0] = sf[t][0] * 0.125f + mb[t][0];
            sv[t][1] = sf[t][1] * 0.125f + mb[t][1];
            sv[t][2] = sf[t][2] * 0.125f + mb[t][0];
            sv[t][3] = sf[t][3] * 0.125f + mb[t][1];
        }

        // Row maxima (rows gid and gid+8); quad lanes share a row
        float rm0 = -1e30f, rm1 = -1e30f;
        #pragma unroll
        for (int t = 0; t < 4; t++) {
            rm0 = fmaxf(rm0, fmaxf(sv[t][0], sv[t][1]));
            rm1 = fmaxf(rm1, fmaxf(sv[t][2], sv[t][3]));
        }
        rm0 = fmaxf(rm0, __shfl_xor_sync(0xffffffffu, rm0, 1));
        rm0 = fmaxf(rm0, __shfl_xor_sync(0xffffffffu, rm0, 2));
        rm1 = fmaxf(rm1, __shfl_xor_sync(0xffffffffu, rm1, 1));
        rm1 = fmaxf(rm1, __shfl_xor_sync(0xffffffffu, rm1, 2));

        float mn0 = fmaxf(m_i[0], rm0);
        float mn1 = fmaxf(m_i[1], rm1);
        float corr0 = __expf(m_i[0] - mn0);
        float corr1 = __expf(m_i[1] - mn1);

        float p[4][4];
        float rs0 = 0.0f, rs1 = 0.0f;
        #pragma unroll
        for (int t = 0; t < 4; t++) {
            p[t][0] = __expf(sv[t][0] - mn0);
            p[t][1] = __expf(sv[t][1] - mn0);
            p[t][2] = __expf(sv[t][2] - mn1);
            p[t][3] = __expf(sv[t][3] - mn1);
            rs0 += p[t][0] + p[t][1];
            rs1 += p[t][2] + p[t][3];
        }
        rs0 += __shfl_xor_sync(0xffffffffu, rs0, 1);
        rs0 += __shfl_xor_sync(0xffffffffu, rs0, 2);
        rs1 += __shfl_xor_sync(0xffffffffu, rs1, 1);
        rs1 += __shfl_xor_sync(0xffffffffu, rs1, 2);

        l_i[0] = l_i[0] * corr0 + rs0;
        l_i[1] = l_i[1] * corr1 + rs1;
        m_i[0] = mn0;
        m_i[1] = mn1;
        #pragma unroll
        for (int t = 0; t < 8; t++) {
            of[t][0] *= corr0; of[t][1] *= corr0;
            of[t][2] *= corr1; of[t][3] *= corr1;
        }

        // Write P (tf32) to union buffer, stride PSTR; warp-local rows only
        #pragma unroll
        for (int t = 0; t < 4; t++) {
            int col = t * 8 + 2 * tig;
            uint2 p01 = make_uint2(f2tf32(p[t][0]), f2tf32(p[t][1]));
            uint2 p23 = make_uint2(f2tf32(p[t][2]), f2tf32(p[t][3]));
            *(uint2*)&KPs[(wrow + gid) * PSTR + col] = p01;
            *(uint2*)&KPs[(wrow + gid + 8) * PSTR + col] = p23;
        }

        // PV: m16 x n64, k=32 -> 4 ksteps x 8 ntiles
        #pragma unroll
        for (int ks = 0; ks < 4; ks++) {
            int kb = ks * 8;
            uint32_t af[4];
            af[0] = KPs[(wrow + gid) * PSTR + kb + tig];
            af[1] = KPs[(wrow + gid + 8) * PSTR + kb + tig];
            af[2] = KPs[(wrow + gid) * PSTR + kb + tig + 4];
            af[3] = KPs[(wrow + gid + 8) * PSTR + kb + tig + 4];
            #pragma unroll
            for (int t = 0; t < 8; t++) {
                uint32_t bf[2];
                bf[0] = Vs[(kb + tig) * VSTR + t * 8 + gid];
                bf[1] = Vs[(kb + tig + 4) * VSTR + t * 8 + gid];
                mma_tf32(of[t], af, bf);
            }
        }
    }

    // Epilogue: normalize and write ctx
    float inv0 = 1.0f / l_i[0];
    float inv1 = 1.0f / l_i[1];
    int r0 = rowbase + q0 + wrow + gid;
    int r1 = r0 + 8;
    #pragma unroll
    for (int t = 0; t < 8; t++) {
        int col = h * HD + t * 8 + 2 * tig;
        *(float2*)&g_ctx[(size_t)r0 * HH + col] =
            make_float2(of[t][0] * inv0, of[t][1] * inv0);
        *(float2*)&g_ctx[(size_t)r1 * HH + col] =
            make_float2(of[t][2] * inv1, of[t][3] * inv1);
    }
}

// ---------------------------------------------------------------------------
// Launch
// ---------------------------------------------------------------------------
extern "C" void kernel_launch(void* const* d_in, const int* in_sizes, int n_in,
                              void* d_out, int out_size) {
    (void)in_sizes; (void)n_in; (void)out_size;
    const float* x      = (const float*)d_in[0];
    const int*   mask   = (const int*)d_in[1];
    const float* qkv_w  = (const float*)d_in[2];
    const float* qkv_b  = (const float*)d_in[3];
    const float* out_w  = (const float*)d_in[4];
    const float* out_b  = (const float*)d_in[5];
    const float* gamma  = (const float*)d_in[6];
    const float* beta   = (const float*)d_in[7];
    float* out = (float*)d_out;

    float *py = nullptr, *pqkv = nullptr, *pctx = nullptr;
    cudaGetSymbolAddress((void**)&py,   g_y);
    cudaGetSymbolAddress((void**)&pqkv, g_qkv);
    cudaGetSymbolAddress((void**)&pctx, g_ctx);

    // 1) pre-LayerNorm
    ln_kernel<<<MROWS, 256>>>(x, gamma, beta);

    // 2) QKV projection: [8192,1024] @ [3072,1024]^T + b -> [8192,3072]
    gemm_tc_kernel<3 * HH, HH, false>
        <<<dim3(3 * HH / 128, MROWS / 128), 256>>>(py, qkv_w, qkv_b, nullptr, pqkv);

    // 3) Flash attention -> g_ctx
    attn_kernel<<<dim3(SS / TQ, NH, BB), 128>>>(mask);

    // 4) Output projection + bias + residual
    gemm_tc_kernel<HH, HH, true>
        <<<dim3(HH / 128, MROWS / 128), 256>>>(pctx, out_w, out_b, x, out);
}

// round 3
// speedup vs baseline: 7.1464x; 2.2625x over previous
#include <cuda_runtime.h>
#include <cuda_bf16.h>
#include <math.h>
#include <stdint.h>

// Problem constants (fixed by setup_inputs)
#define BB 4
#define SS 2048
#define HH 1024
#define NH 16
#define HD 64
#define MROWS (BB * SS)          // 8192
#define LN_EPS 1e-5f

// ---------------------------------------------------------------------------
// Scratch (device globals: no allocation allowed in kernel_launch)
// ---------------------------------------------------------------------------
__device__ __nv_bfloat16 g_ybf[MROWS * HH];          // LN output (bf16)
__device__ __nv_bfloat16 g_qkvbf[MROWS * 3 * HH];    // QKV (bf16)
__device__ __nv_bfloat16 g_ctxbf[MROWS * HH];        // attention ctx (bf16)
__device__ __nv_bfloat16 g_wqkv[3 * HH * HH];        // qkv_w bf16
__device__ __nv_bfloat16 g_wout[HH * HH];            // out_w bf16

// ---------------------------------------------------------------------------
// Helpers
// ---------------------------------------------------------------------------
__device__ __forceinline__ uint32_t packbf(float x, float y) {
    __nv_bfloat162 h = __float22bfloat162_rn(make_float2(x, y));
    return *reinterpret_cast<uint32_t*>(&h);
}

__device__ __forceinline__ void mma_bf16(float* c, const uint32_t* a, const uint32_t* b) {
    asm volatile(
        "mma.sync.aligned.m16n8k16.row.col.f32.bf16.bf16.f32 "
        "{%0,%1,%2,%3}, {%4,%5,%6,%7}, {%8,%9}, {%0,%1,%2,%3};"
        : "+f"(c[0]), "+f"(c[1]), "+f"(c[2]), "+f"(c[3])
        : "r"(a[0]), "r"(a[1]), "r"(a[2]), "r"(a[3]), "r"(b[0]), "r"(b[1]));
}

__device__ __forceinline__ void ldsm_x4(uint32_t& r0, uint32_t& r1, uint32_t& r2,
                                        uint32_t& r3, uint32_t addr) {
    asm volatile("ldmatrix.sync.aligned.m8n8.x4.shared.b16 {%0,%1,%2,%3}, [%4];"
                 : "=r"(r0), "=r"(r1), "=r"(r2), "=r"(r3) : "r"(addr));
}
__device__ __forceinline__ void ldsm_x4_t(uint32_t& r0, uint32_t& r1, uint32_t& r2,
                                          uint32_t& r3, uint32_t addr) {
    asm volatile("ldmatrix.sync.aligned.m8n8.x4.trans.shared.b16 {%0,%1,%2,%3}, [%4];"
                 : "=r"(r0), "=r"(r1), "=r"(r2), "=r"(r3) : "r"(addr));
}

#define CP_A16(dst, src) \
    asm volatile("cp.async.cg.shared.global [%0], [%1], 16;\n" :: "r"(dst), "l"(src))
#define CP_COMMIT() asm volatile("cp.async.commit_group;\n")
#define CP_WAIT1() asm volatile("cp.async.wait_group 1;\n")
#define CP_WAIT0() asm volatile("cp.async.wait_group 0;\n")

// SW128 swizzle for 128-byte rows: chunk (16B) XOR (row & 7)
__device__ __forceinline__ uint32_t swz(int row, int chunk) {
    return (uint32_t)(row * 128 + ((chunk ^ (row & 7)) << 4));
}

// ---------------------------------------------------------------------------
// fp32 -> bf16 convert (weights), 4 elems/thread
// ---------------------------------------------------------------------------
__global__ __launch_bounds__(256) void f2bf_kernel(const float* __restrict__ in,
                                                   __nv_bfloat16* __restrict__ out) {
    int i = blockIdx.x * blockDim.x + threadIdx.x;
    float4 v = ((const float4*)in)[i];
    uint2 o;
    o.x = packbf(v.x, v.y);
    o.y = packbf(v.z, v.w);
    ((uint2*)out)[i] = o;
}

// ---------------------------------------------------------------------------
// LayerNorm: one block per row, 256 threads, bf16 output
// ---------------------------------------------------------------------------
__device__ __forceinline__ float block_reduce_sum_256(float v, float* sbuf) {
    #pragma unroll
    for (int off = 16; off > 0; off >>= 1)
        v += __shfl_xor_sync(0xffffffffu, v, off);
    int wid = threadIdx.x >> 5;
    if ((threadIdx.x & 31) == 0) sbuf[wid] = v;
    __syncthreads();
    if (threadIdx.x < 32) {
        float t = (threadIdx.x < 8) ? sbuf[threadIdx.x] : 0.0f;
        #pragma unroll
        for (int off = 4; off > 0; off >>= 1)
            t += __shfl_xor_sync(0xffffffffu, t, off);
        if (threadIdx.x == 0) sbuf[0] = t;
    }
    __syncthreads();
    float r = sbuf[0];
    __syncthreads();
    return r;
}

__global__ __launch_bounds__(256) void ln_kernel(const float* __restrict__ x,
                                                 const float* __restrict__ gamma,
                                                 const float* __restrict__ beta) {
    __shared__ float sbuf[8];
    int row = blockIdx.x;
    int t = threadIdx.x;
    const float4* xr = (const float4*)(x + (size_t)row * HH);
    float4 v = xr[t];
    float s = v.x + v.y + v.z + v.w;
    s = block_reduce_sum_256(s, sbuf);
    float mu = s * (1.0f / HH);
    float dx0 = v.x - mu, dx1 = v.y - mu, dx2 = v.z - mu, dx3 = v.w - mu;
    float sq = dx0 * dx0 + dx1 * dx1 + dx2 * dx2 + dx3 * dx3;
    sq = block_reduce_sum_256(sq, sbuf);
    float rstd = rsqrtf(sq * (1.0f / HH) + LN_EPS);
    float4 gg = ((const float4*)gamma)[t];
    float4 bb = ((const float4*)beta)[t];
    uint2 o;
    o.x = packbf(dx0 * rstd * gg.x + bb.x, dx1 * rstd * gg.y + bb.y);
    o.y = packbf(dx2 * rstd * gg.z + bb.z, dx3 * rstd * gg.w + bb.w);
    ((uint2*)(g_ybf + (size_t)row * HH))[t] = o;
}

// ---------------------------------------------------------------------------
// bf16 tensor-core GEMM: C = A @ W^T + bias (+resid)
// Block 128x128, BK=64, 256 threads = 8 warps, warp tile 64x32.
// cp.async 2-stage pipeline, SW128 swizzle, ldmatrix fragments.
// smem: dynamic 64KB = A0,A1,B0,B1 x 16KB
// ---------------------------------------------------------------------------
template <int N, int K, bool OUT_FP32>
__global__ __launch_bounds__(256) void gemm_bf16_kernel(
    const __nv_bfloat16* __restrict__ A,
    const __nv_bfloat16* __restrict__ W,
    const float* __restrict__ bias,
    const float* __restrict__ resid,
    float* __restrict__ Cf,
    __nv_bfloat16* __restrict__ Cb) {
    extern __shared__ uint8_t smem[];
    uint32_t sbase = (uint32_t)__cvta_generic_to_shared(smem);

    int m0 = blockIdx.y * 128;
    int n0 = blockIdx.x * 128;
    int tid = threadIdx.x;
    int warp = tid >> 5, lane = tid & 31;
    int wm = warp >> 2, wn = warp & 3;

    float acc[4][4][4];
    #pragma unroll
    for (int i = 0; i < 4; i++)
        #pragma unroll
        for (int j = 0; j < 4; j++)
            #pragma unroll
            for (int r = 0; r < 4; r++) acc[i][j][r] = 0.0f;

    // per-thread load coords: lin = tid + i*256; row = lin>>3; chunk = lin&7
    int lrow = tid >> 3;
    int lc = tid & 7;

    #pragma unroll 1
    for (int pre = 0; pre < 1; pre++) {
        #pragma unroll
        for (int i = 0; i < 4; i++) {
            int row = lrow + i * 32;
            uint32_t sw = swz(row, lc);
            CP_A16(sbase + sw, A + (size_t)(m0 + row) * K + lc * 8);
            CP_A16(sbase + 32768 + sw, W + (size_t)(n0 + row) * K + lc * 8);
        }
        CP_COMMIT();
    }

    const int NK = K / 64;
    for (int kt = 0; kt < NK; kt++) {
        if (kt + 1 < NK) {
            int k0 = (kt + 1) * 64;
            uint32_t stoff = ((kt + 1) & 1) * 16384;
            #pragma unroll
            for (int i = 0; i < 4; i++) {
                int row = lrow + i * 32;
                uint32_t sw = swz(row, lc) + stoff;
                CP_A16(sbase + sw, A + (size_t)(m0 + row) * K + k0 + lc * 8);
                CP_A16(sbase + 32768 + sw, W + (size_t)(n0 + row) * K + k0 + lc * 8);
            }
            CP_COMMIT();
            CP_WAIT1();
        } else {
            CP_WAIT0();
        }
        __syncthreads();

        uint32_t ab = sbase + (kt & 1) * 16384;
        uint32_t bb = sbase + 32768 + (kt & 1) * 16384;

        #pragma unroll
        for (int ks = 0; ks < 4; ks++) {
            uint32_t af[4][4];
            #pragma unroll
            for (int tm = 0; tm < 4; tm++) {
                int r = wm * 64 + tm * 16 + (lane & 15);
                int chunk = ks * 2 + (lane >> 4);
                ldsm_x4(af[tm][0], af[tm][1], af[tm][2], af[tm][3], ab + swz(r, chunk));
            }
            uint32_t bf[4][2];
            #pragma unroll
            for (int tp = 0; tp < 2; tp++) {
                int r = wn * 32 + tp * 16 + (lane & 7) + ((lane >> 4) << 3);
                int chunk = ks * 2 + ((lane >> 3) & 1);
                ldsm_x4(bf[2 * tp][0], bf[2 * tp][1], bf[2 * tp + 1][0],
                        bf[2 * tp + 1][1], bb + swz(r, chunk));
            }
            #pragma unroll
            for (int tm = 0; tm < 4; tm++)
                #pragma unroll
                for (int tn = 0; tn < 4; tn++)
                    mma_bf16(acc[tm][tn], af[tm], bf[tn]);
        }
        __syncthreads();
    }

    // Epilogue
    int gid = lane >> 2, tig = lane & 3;
    #pragma unroll
    for (int tm = 0; tm < 4; tm++) {
        int m = m0 + wm * 64 + tm * 16 + gid;
        #pragma unroll
        for (int tn = 0; tn < 4; tn++) {
            int n = n0 + wn * 32 + tn * 8 + 2 * tig;
            float b0 = bias[n], b1 = bias[n + 1];
            float v0 = acc[tm][tn][0] + b0;
            float v1 = acc[tm][tn][1] + b1;
            float v2 = acc[tm][tn][2] + b0;
            float v3 = acc[tm][tn][3] + b1;
            if (OUT_FP32) {
                v0 += resid[(size_t)m * N + n];
                v1 += resid[(size_t)m * N + n + 1];
                v2 += resid[(size_t)(m + 8) * N + n];
                v3 += resid[(size_t)(m + 8) * N + n + 1];
                *(float2*)&Cf[(size_t)m * N + n] = make_float2(v0, v1);
                *(float2*)&Cf[(size_t)(m + 8) * N + n] = make_float2(v2, v3);
            } else {
                *(uint32_t*)&Cb[(size_t)m * N + n] = packbf(v0, v1);
                *(uint32_t*)&Cb[(size_t)(m + 8) * N + n] = packbf(v2, v3);
            }
        }
    }
}

// ---------------------------------------------------------------------------
// Flash attention, bf16 mma. Grid (S/64, NH, B), 128 threads = 4 warps.
// Warp owns 16 q-rows. KV tiles of 32 rows, cp.async double-buffered.
// P stays in registers (score C-frag == PV A-frag layout).
// ---------------------------------------------------------------------------
#define TQ 64
#define TK 32

__global__ __launch_bounds__(128) void attn_kernel(const int* __restrict__ mask) {
    __shared__ alignas(16) uint8_t sQ[TQ * 128];        // 8KB
    __shared__ alignas(16) uint8_t sK[2][TK * 128];     // 8KB
    __shared__ alignas(16) uint8_t sV[2][TK * 128];     // 8KB

    int tid = threadIdx.x;
    int warp = tid >> 5, lane = tid & 31;
    int gid = lane >> 2, tig = lane & 3;
    int qt = blockIdx.x, h = blockIdx.y, b = blockIdx.z;
    int q0 = qt * TQ;
    int rowbase = b * SS;
    const int LD = 3 * HH;
    const __nv_bfloat16* qkv = g_qkvbf;
    int wrow = warp * 16;

    uint32_t qB = (uint32_t)__cvta_generic_to_shared(sQ);
    uint32_t kB0 = (uint32_t)__cvta_generic_to_shared(sK[0]);
    uint32_t vB0 = (uint32_t)__cvta_generic_to_shared(sV[0]);

    int lrow = tid >> 3;      // 0..15
    int lc = tid & 7;

    // Q: 64 rows x 8 chunks = 512 / 128 threads = 4 each
    #pragma unroll
    for (int i = 0; i < 4; i++) {
        int row = lrow + i * 16;
        CP_A16(qB + swz(row, lc),
               qkv + (size_t)(rowbase + q0 + row) * LD + h * HD + lc * 8);
    }
    // KV tile 0: 32 rows x 8 chunks x2 = 512 / 128 = 4 each
    #pragma unroll
    for (int i = 0; i < 2; i++) {
        int row = lrow + i * 16;
        uint32_t sw = swz(row, lc);
        const __nv_bfloat16* base =
            qkv + (size_t)(rowbase + row) * LD + h * HD + lc * 8;
        CP_A16(kB0 + sw, base + HH);
        CP_A16(vB0 + sw, base + 2 * HH);
    }
    CP_COMMIT();

    float m_i[2] = {-1e30f, -1e30f};
    float l_i[2] = {0.0f, 0.0f};
    float of[8][4];
    #pragma unroll
    for (int t = 0; t < 8; t++)
        #pragma unroll
        for (int r = 0; r < 4; r++) of[t][r] = 0.0f;

    const int NKT = SS / TK;   // 64
    for (int kt = 0; kt < NKT; kt++) {
        if (kt + 1 < NKT) {
            int k0n = (kt + 1) * TK;
            uint32_t stoff = ((kt + 1) & 1) * (TK * 128);
            #pragma unroll
            for (int i = 0; i < 2; i++) {
                int row = lrow + i * 16;
                uint32_t sw = swz(row, lc) + stoff;
                const __nv_bfloat16* base =
                    qkv + (size_t)(rowbase + k0n + row) * LD + h * HD + lc * 8;
                CP_A16(kB0 + sw, base + HH);
                CP_A16(vB0 + sw, base + 2 * HH);
            }
            CP_COMMIT();
            CP_WAIT1();
        } else {
            CP_WAIT0();
        }
        __syncthreads();

        uint32_t kb = kB0 + (kt & 1) * (TK * 128);
        uint32_t vb = vB0 + (kt & 1) * (TK * 128);
        int k0 = kt * TK;

        // ---- scores: m16 x n32, k=64 -> 4 ksteps x 4 ntiles
        float sf[4][4];
        #pragma unroll
        for (int t = 0; t < 4; t++)
            #pragma unroll
            for (int r = 0; r < 4; r++) sf[t][r] = 0.0f;

        #pragma unroll
        for (int ks = 0; ks < 4; ks++) {
            uint32_t aq[4];
            {
                int r = wrow + (lane & 15);
                int chunk = ks * 2 + (lane >> 4);
                ldsm_x4(aq[0], aq[1], aq[2], aq[3], qB + swz(r, chunk));
            }
            uint32_t bk[4][2];
            #pragma unroll
            for (int tp = 0; tp < 2; tp++) {
                int r = tp * 16 + (lane & 7) + ((lane >> 4) << 3);
                int chunk = ks * 2 + ((lane >> 3) & 1);
                ldsm_x4(bk[2 * tp][0], bk[2 * tp][1], bk[2 * tp + 1][0],
                        bk[2 * tp + 1][1], kb + swz(r, chunk));
            }
            #pragma unroll
            for (int t = 0; t < 4; t++) mma_bf16(sf[t], aq, bk[t]);
        }

        // ---- softmax (fp32)
        float sv[4][4];
        #pragma unroll
        for (int t = 0; t < 4; t++) {
            int col = k0 + t * 8 + 2 * tig;
            float mb0 = (float)mask[b * SS + col] * -1e8f;
            float mb1 = (float)mask[b * SS + col + 1] * -1e8f;
            sv[t][0] = sf[t][0] * 0.125f + mb0;
            sv[t][1] = sf[t][1] * 0.125f + mb1;
            sv[t][2] = sf[t][2] * 0.125f + mb0;
            sv[t][3] = sf[t][3] * 0.125f + mb1;
        }
        float rm0 = -1e30f, rm1 = -1e30f;
        #pragma unroll
        for (int t = 0; t < 4; t++) {
            rm0 = fmaxf(rm0, fmaxf(sv[t][0], sv[t][1]));
            rm1 = fmaxf(rm1, fmaxf(sv[t][2], sv[t][3]));
        }
        rm0 = fmaxf(rm0, __shfl_xor_sync(0xffffffffu, rm0, 1));
        rm0 = fmaxf(rm0, __shfl_xor_sync(0xffffffffu, rm0, 2));
        rm1 = fmaxf(rm1, __shfl_xor_sync(0xffffffffu, rm1, 1));
        rm1 = fmaxf(rm1, __shfl_xor_sync(0xffffffffu, rm1, 2));

        float mn0 = fmaxf(m_i[0], rm0);
        float mn1 = fmaxf(m_i[1], rm1);
        float corr0 = __expf(m_i[0] - mn0);
        float corr1 = __expf(m_i[1] - mn1);

        float p[4][4];
        float rs0 = 0.0f, rs1 = 0.0f;
        #pragma unroll
        for (int t = 0; t < 4; t++) {
            p[t][0] = __expf(sv[t][0] - mn0);
            p[t][1] = __expf(sv[t][1] - mn0);
            p[t][2] = __expf(sv[t][2] - mn1);
            p[t][3] = __expf(sv[t][3] - mn1);
            rs0 += p[t][0] + p[t][1];
            rs1 += p[t][2] + p[t][3];
        }
        rs0 += __shfl_xor_sync(0xffffffffu, rs0, 1);
        rs0 += __shfl_xor_sync(0xffffffffu, rs0, 2);
        rs1 += __shfl_xor_sync(0xffffffffu, rs1, 1);
        rs1 += __shfl_xor_sync(0xffffffffu, rs1, 2);

        l_i[0] = l_i[0] * corr0 + rs0;
        l_i[1] = l_i[1] * corr1 + rs1;
        m_i[0] = mn0;
        m_i[1] = mn1;
        #pragma unroll
        for (int t = 0; t < 8; t++) {
            of[t][0] *= corr0; of[t][1] *= corr0;
            of[t][2] *= corr1; of[t][3] *= corr1;
        }

        // ---- PV: A = P in registers, B = V via ldmatrix.trans
        // k (seq) = 32 -> 2 ksteps of 16; n (hd) = 64 -> 8 ntiles
        #pragma unroll
        for (int ks = 0; ks < 2; ks++) {
            uint32_t ap[4];
            ap[0] = packbf(p[2 * ks][0], p[2 * ks][1]);
            ap[1] = packbf(p[2 * ks][2], p[2 * ks][3]);
            ap[2] = packbf(p[2 * ks + 1][0], p[2 * ks + 1][1]);
            ap[3] = packbf(p[2 * ks + 1][2], p[2 * ks + 1][3]);
            #pragma unroll
            for (int tp = 0; tp < 4; tp++) {
                uint32_t bv[4];
                int r = ks * 16 + (lane & 7) + ((lane >> 3) & 1) * 8;
                int chunk = 2 * tp + (lane >> 4);
                ldsm_x4_t(bv[0], bv[1], bv[2], bv[3], vb + swz(r, chunk));
                mma_bf16(of[2 * tp], ap, &bv[0]);
                mma_bf16(of[2 * tp + 1], ap, &bv[2]);
            }
        }
        __syncthreads();
    }

    // Epilogue: normalize, pack to bf16 ctx
    float inv0 = 1.0f / l_i[0];
    float inv1 = 1.0f / l_i[1];
    int r0 = rowbase + q0 + wrow + gid;
    int r1 = r0 + 8;
    #pragma unroll
    for (int t = 0; t < 8; t++) {
        int col = h * HD + t * 8 + 2 * tig;
        *(uint32_t*)&g_ctxbf[(size_t)r0 * HH + col] =
            packbf(of[t][0] * inv0, of[t][1] * inv0);
        *(uint32_t*)&g_ctxbf[(size_t)r1 * HH + col] =
            packbf(of[t][2] * inv1, of[t][3] * inv1);
    }
}

// ---------------------------------------------------------------------------
// Launch
// ---------------------------------------------------------------------------
extern "C" void kernel_launch(void* const* d_in, const int* in_sizes, int n_in,
                              void* d_out, int out_size) {
    (void)in_sizes; (void)n_in; (void)out_size;
    const float* x      = (const float*)d_in[0];
    const int*   mask   = (const int*)d_in[1];
    const float* qkv_w  = (const float*)d_in[2];
    const float* qkv_b  = (const float*)d_in[3];
    const float* out_w  = (const float*)d_in[4];
    const float* out_b  = (const float*)d_in[5];
    const float* gamma  = (const float*)d_in[6];
    const float* beta   = (const float*)d_in[7];
    float* out = (float*)d_out;

    __nv_bfloat16 *pwqkv = nullptr, *pwout = nullptr, *py = nullptr,
                  *pqkv = nullptr, *pctx = nullptr;
    cudaGetSymbolAddress((void**)&pwqkv, g_wqkv);
    cudaGetSymbolAddress((void**)&pwout, g_wout);
    cudaGetSymbolAddress((void**)&py,    g_ybf);
    cudaGetSymbolAddress((void**)&pqkv,  g_qkvbf);
    cudaGetSymbolAddress((void**)&pctx,  g_ctxbf);

    // enable 64KB dynamic smem for the GEMMs (idempotent)
    cudaFuncSetAttribute(gemm_bf16_kernel<3 * HH, HH, false>,
                         cudaFuncAttributeMaxDynamicSharedMemorySize, 65536);
    cudaFuncSetAttribute(gemm_bf16_kernel<HH, HH, true>,
                         cudaFuncAttributeMaxDynamicSharedMemorySize, 65536);

    // 0) weight conversion fp32 -> bf16
    f2bf_kernel<<<(3 * HH * HH / 4) / 256, 256>>>(qkv_w, pwqkv);
    f2bf_kernel<<<(HH * HH / 4) / 256, 256>>>(out_w, pwout);

    // 1) pre-LayerNorm -> bf16
    ln_kernel<<<MROWS, 256>>>(x, gamma, beta);

    // 2) QKV projection (bf16 out)
    gemm_bf16_kernel<3 * HH, HH, false>
        <<<dim3(3 * HH / 128, MROWS / 128), 256, 65536>>>(
            py, pwqkv, qkv_b, nullptr, nullptr, pqkv);

    // 3) Flash attention -> bf16 ctx
    attn_kernel<<<dim3(SS / TQ, NH, BB), 128>>>(mask);

    // 4) Output projection + bias + residual (fp32 out)
    gemm_bf16_kernel<HH, HH, true>
        <<<dim3(HH / 128, MROWS / 128), 256, 65536>>>(
            pctx, pwout, out_b, x, out, nullptr);
}